// round 17
// baseline (speedup 1.0000x reference)
#include <cuda_runtime.h>
#include <cuda_bf16.h>
#include <cstdint>

// ===========================================================================
// SparseMotionEncoder — round 17: producer-side bf16 hi/lo split planes.
// Tap GEMM A-loads become pure cp.async (zfill for invalid rows) from
// pre-split planes: no register staging / conversion in the tensor mainloop.
//  - c1 tmma + flow_conv write hi/lo planes directly
//  - cat: fp32 atomic accumulate -> relu_split pass -> cat planes
//  - stream fork/join graph parallelism as in round 14
// Numerics: bf16x3 split (Ah*Bh + Al*Bh + Ah*Bl), fp32 accum. rel_err ~2e-6.
// ===========================================================================

#define NVOX 50000

__device__ __nv_bfloat16 g_c1h[NVOX * 256], g_c1l[NVOX * 256];
__device__ __nv_bfloat16 g_f1h[NVOX * 128], g_f1l[NVOX * 128];
__device__ __nv_bfloat16 g_cath[NVOX * 256], g_catl[NVOX * 256];
__device__ float g_cat[NVOX * 256];

__device__ int  g_cnt3[27];
__device__ int2 g_list3[27 * NVOX];     // (in_idx, out_idx) per tap
__device__ int  g_nitems;
__device__ int  g_items[10560];         // packed: tap | (mtile << 5)

// Transposed, split weights: [KK][COUTPAD][CINPAD] bf16, zero padded.
__device__ __nv_bfloat16 gW_c1_hi[1 * 256 * 352], gW_c1_lo[1 * 256 * 352];
__device__ __nv_bfloat16 gW_c2_hi[27 * 192 * 256], gW_c2_lo[27 * 192 * 256];
__device__ __nv_bfloat16 gW_f2_hi[27 * 64 * 128],  gW_f2_lo[27 * 64 * 128];
__device__ __nv_bfloat16 gW_ct_hi[27 * 128 * 256], gW_ct_lo[27 * 128 * 256];

__device__ __forceinline__ uint32_t pkbf(float a, float b) {
    __nv_bfloat162 t = __floats2bfloat162_rn(a, b);
    return *reinterpret_cast<uint32_t*>(&t);
}
__device__ __forceinline__ void mma16816(float* c, const uint32_t* a,
                                         const uint32_t* b) {
    asm volatile(
        "mma.sync.aligned.m16n8k16.row.col.f32.bf16.bf16.f32 "
        "{%0,%1,%2,%3}, {%4,%5,%6,%7}, {%8,%9}, {%0,%1,%2,%3};"
        : "+f"(c[0]), "+f"(c[1]), "+f"(c[2]), "+f"(c[3])
        : "r"(a[0]), "r"(a[1]), "r"(a[2]), "r"(a[3]), "r"(b[0]), "r"(b[1]));
}
__device__ __forceinline__ void ldsm4(uint32_t* r, uint32_t addr) {
    asm volatile(
        "ldmatrix.sync.aligned.m8n8.x4.shared.b16 {%0,%1,%2,%3}, [%4];"
        : "=r"(r[0]), "=r"(r[1]), "=r"(r[2]), "=r"(r[3]) : "r"(addr));
}
__device__ __forceinline__ void cpasync16(uint32_t dst, const void* src) {
    asm volatile("cp.async.cg.shared.global [%0], [%1], 16;" :: "r"(dst), "l"(src));
}
// zero-fill variant: bytes beyond srcsz come in as 0 (srcsz 0 or 16)
__device__ __forceinline__ void cpasync16z(uint32_t dst, const void* src, uint32_t srcsz) {
    asm volatile("cp.async.cg.shared.global [%0], [%1], 16, %2;"
                 :: "r"(dst), "l"(src), "r"(srcsz));
}
__device__ __forceinline__ void red4(float* p, float4 v) {
    asm volatile("red.global.add.v4.f32 [%0], {%1,%2,%3,%4};"
                 :: "l"(p), "f"(v.x), "f"(v.y), "f"(v.z), "f"(v.w) : "memory");
}
#define CP_COMMIT() asm volatile("cp.async.commit_group;" ::: "memory")
#define CP_WAIT0()  asm volatile("cp.async.wait_group 0;" ::: "memory")

// ---------------------------------------------------------------------------
template <int KK, int CIN, int COUT, int CINPAD, int COUTPAD>
__global__ void prep_w(const float* __restrict__ W,
                       __nv_bfloat16* __restrict__ hi,
                       __nv_bfloat16* __restrict__ lo)
{
    long tid = (long)blockIdx.x * blockDim.x + threadIdx.x;
    const long total = (long)KK * COUTPAD * CINPAD;
    if (tid >= total) return;
    int c = tid % CINPAD;
    long r = tid / CINPAD;
    int n = r % COUTPAD;
    int k = r / COUTPAD;
    float x = (c < CIN && n < COUT) ? W[((size_t)k * CIN + c) * COUT + n] : 0.f;
    __nv_bfloat16 h = __float2bfloat16(x);
    hi[tid] = h;
    lo[tid] = __float2bfloat16(x - __bfloat162float(h));
}

// ---------------------------------------------------------------------------
__global__ void zero_cnt()
{
    if (threadIdx.x < 27) g_cnt3[threadIdx.x] = 0;
    if (threadIdx.x == 31) g_nitems = 0;
}

__global__ void build_list(const int* __restrict__ nbr, int N)
{
    const int k = blockIdx.y;
    const int n = blockIdx.x * 256 + threadIdx.x;
    const int lane = threadIdx.x & 31;
    int idx = -1;
    if (n < N) idx = nbr[(size_t)k * N + n];
    const bool v = idx >= 0;
    unsigned m = __ballot_sync(0xffffffffu, v);
    if (!m) return;
    int leader = __ffs(m) - 1;
    int base = 0;
    if (lane == leader) base = atomicAdd(&g_cnt3[k], __popc(m));
    base = __shfl_sync(0xffffffffu, base, leader);
    if (v) {
        int pos = base + __popc(m & ((1u << lane) - 1u));
        g_list3[(size_t)k * NVOX + pos] = make_int2(idx, n);
    }
}

__global__ void sched()
{
    int k = threadIdx.x;
    if (k < 27) {
        int tiles = (g_cnt3[k] + 127) >> 7;
        int base = atomicAdd(&g_nitems, tiles);
        for (int i = 0; i < tiles; ++i)
            g_items[base + i] = k | (i << 5);
    }
}

// ---------------------------------------------------------------------------
__global__ void init_cat(float* __restrict__ cat,
                         const float* __restrict__ b0,   // 192
                         const float* __restrict__ b1,   // 64
                         int N)
{
    long i = (long)blockIdx.x * blockDim.x + threadIdx.x;
    if (i >= (long)N * 256) return;
    int c = i & 255;
    cat[i] = (c < 192) ? b0[c] : b1[c - 192];
}

__global__ void init_bias(float* __restrict__ out, int ostride, int ocol,
                          const float* __restrict__ bias, int COUT, int N)
{
    long i = (long)blockIdx.x * blockDim.x + threadIdx.x;
    if (i >= (long)N * COUT) return;
    int r = i / COUT, c = i % COUT;
    out[(size_t)r * ostride + ocol + c] = bias[c];
}

__global__ void relu_region(float* __restrict__ p, int stride, int ocol,
                            int COUT, int N)
{
    long i = (long)blockIdx.x * blockDim.x + threadIdx.x;
    if (i >= (long)N * COUT) return;
    int r = i / COUT, c = i % COUT;
    float* q = p + (size_t)r * stride + ocol + c;
    *q = fmaxf(*q, 0.f);
}

// relu + hi/lo split: fp32 buffer -> two bf16 planes (4 elems / thread)
__global__ void relu_split(const float* __restrict__ src,
                           __nv_bfloat16* __restrict__ hi,
                           __nv_bfloat16* __restrict__ lo, long total)
{
    long i = ((long)blockIdx.x * blockDim.x + threadIdx.x) * 4;
    if (i >= total) return;
    float4 v = *reinterpret_cast<const float4*>(src + i);
    v.x = fmaxf(v.x, 0.f); v.y = fmaxf(v.y, 0.f);
    v.z = fmaxf(v.z, 0.f); v.w = fmaxf(v.w, 0.f);
    float hx = __bfloat162float(__float2bfloat16(v.x));
    float hy = __bfloat162float(__float2bfloat16(v.y));
    float hz = __bfloat162float(__float2bfloat16(v.z));
    float hw = __bfloat162float(__float2bfloat16(v.w));
    *reinterpret_cast<uint2*>(hi + i) = make_uint2(pkbf(v.x, v.y), pkbf(v.z, v.w));
    *reinterpret_cast<uint2*>(lo + i) =
        make_uint2(pkbf(v.x - hx, v.y - hy), pkbf(v.z - hz, v.w - hw));
}

// ---------------------------------------------------------------------------
// Dense pipelined HMMA gather-GEMM (identity rows) — c1 only.
// Epilogue writes relu(bias+acc) as bf16 hi/lo planes.
// ---------------------------------------------------------------------------
template <int KK, int CIN, int CINPAD, int NT>
__global__ void __launch_bounds__(256, 2)
tmma(const float* __restrict__ feat, int fstride,
     const __nv_bfloat16* __restrict__ Whi, const __nv_bfloat16* __restrict__ Wlo,
     int COUTPAD, const float* __restrict__ bias,
     __nv_bfloat16* __restrict__ outHi, __nv_bfloat16* __restrict__ outLo,
     int ostride, int COUT, int N)
{
    constexpr bool TAIL = (CIN % 32) != 0;
    constexpr int CH = CINPAD / 32;
    constexpr int ITERS = KK * CH;
    constexpr int WN = NT / 2;
    constexpr int J  = NT / 16;
    constexpr int JP = J / 2;
    constexpr int BQ = (NT * 8) / 256;
    constexpr uint32_t AB = 10240;
    constexpr uint32_t BB = NT * 80;

    extern __shared__ char dyn[];
    const uint32_t sb = (uint32_t)__cvta_generic_to_shared(dyn);

    const int t = threadIdx.x, lane = t & 31, w = t >> 5;
    const int wm = w >> 1, wn = w & 1;
    const int g = lane >> 2, tg = lane & 3;
    const int row0 = blockIdx.x * 128;
    const int n0 = blockIdx.y * NT;

    float acc[2][J][4];
#pragma unroll
    for (int i = 0; i < 2; ++i)
#pragma unroll
        for (int j = 0; j < J; ++j)
#pragma unroll
            for (int q = 0; q < 4; ++q) acc[i][j][q] = 0.f;

    const int gr = t >> 1;
    const int gcb = (t & 1) * 16;
    const int grow = row0 + gr;

    float4 va[4];

    auto gatherA = [&](int it) {
        const int cc = it % CH;
        const float* frow = (grow < N) ? feat + (size_t)grow * fstride : nullptr;
        const int c0 = cc * 32;
#pragma unroll
        for (int i = 0; i < 4; ++i) {
            const int gcol = c0 + gcb + i * 4;
            float4 v = make_float4(0.f, 0.f, 0.f, 0.f);
            if (frow) {
                if (!TAIL || gcol + 3 < CIN) {
                    v = *reinterpret_cast<const float4*>(frow + gcol);
                } else {
                    float tmp[4] = {0.f, 0.f, 0.f, 0.f};
#pragma unroll
                    for (int jj = 0; jj < 4; ++jj)
                        if (gcol + jj < CIN) tmp[jj] = frow[gcol + jj];
                    v = make_float4(tmp[0], tmp[1], tmp[2], tmp[3]);
                }
            }
            va[i] = v;
        }
    };

    auto storeA = [&](int stage) {
        char* base_h = dyn + (stage * 2 + 0) * AB;
        char* base_l = dyn + (stage * 2 + 1) * AB;
        const int roff = gr * 80;
#pragma unroll
        for (int i = 0; i < 4; ++i) {
            float4 v = va[i];
            float hx = __bfloat162float(__float2bfloat16(v.x));
            float hy = __bfloat162float(__float2bfloat16(v.y));
            float hz = __bfloat162float(__float2bfloat16(v.z));
            float hw = __bfloat162float(__float2bfloat16(v.w));
            uint2 uh = make_uint2(pkbf(hx, hy), pkbf(hz, hw));
            uint2 ul = make_uint2(pkbf(v.x - hx, v.y - hy),
                                  pkbf(v.z - hz, v.w - hw));
            const int boff = roff + (gcb + i * 4) * 2;
            *reinterpret_cast<uint2*>(base_h + boff) = uh;
            *reinterpret_cast<uint2*>(base_l + boff) = ul;
        }
    };

    auto issueB = [&](int it, int stage) {
        const int k = it / CH, cc = it % CH;
        const size_t base = ((size_t)k * COUTPAD + n0) * CINPAD + cc * 32;
#pragma unroll
        for (int q = 0; q < BQ; ++q) {
            const int e = t + q * 256;
            const int plane = e / (NT * 4);
            const int re = e - plane * (NT * 4);
            const int row = re >> 2, seg = re & 3;
            const __nv_bfloat16* src =
                (plane ? Wlo : Whi) + base + (size_t)row * CINPAD + seg * 8;
            const uint32_t dst =
                sb + 4 * AB + (uint32_t)(stage * 2 + plane) * BB + row * 80 + seg * 16;
            cpasync16(dst, src);
        }
    };

    gatherA(0);
    issueB(0, 0);
    CP_COMMIT();
    storeA(0);
    CP_WAIT0();
    __syncthreads();

    const int local = lane & 7, grp = lane >> 3;
    const int arow = (grp & 1) * 8 + local;
    const int abyt = (grp >> 1) * 16;
    const int nloc = (grp >> 1) * 8 + local;
    const int bbyt = (grp & 1) * 16;

#pragma unroll 1
    for (int it = 0; it < ITERS; ++it) {
        const int cur = it & 1, nxt = cur ^ 1;
        const bool more = (it + 1 < ITERS);
        if (more) {
            gatherA(it + 1);
            issueB(it + 1, nxt);
            CP_COMMIT();
        }
        const uint32_t aH = sb + (uint32_t)(cur * 2 + 0) * AB;
        const uint32_t aL = sb + (uint32_t)(cur * 2 + 1) * AB;
        const uint32_t bH = sb + 4 * AB + (uint32_t)(cur * 2 + 0) * BB;
        const uint32_t bL = sb + 4 * AB + (uint32_t)(cur * 2 + 1) * BB;
#pragma unroll
        for (int ks = 0; ks < 2; ++ks) {
            uint32_t Ah[2][4], Al[2][4];
#pragma unroll
            for (int i = 0; i < 2; ++i) {
                const uint32_t ao =
                    (uint32_t)((wm * 32 + i * 16 + arow) * 80 + ks * 32 + abyt);
                ldsm4(Ah[i], aH + ao);
                ldsm4(Al[i], aL + ao);
            }
#pragma unroll
            for (int jp = 0; jp < JP; ++jp) {
                const uint32_t bo =
                    (uint32_t)((wn * WN + jp * 16 + nloc) * 80 + ks * 32 + bbyt);
                uint32_t Bh[4], Bl[4];
                ldsm4(Bh, bH + bo);
                ldsm4(Bl, bL + bo);
#pragma unroll
                for (int i = 0; i < 2; ++i) {
                    mma16816(acc[i][2 * jp],     Ah[i], Bh);
                    mma16816(acc[i][2 * jp],     Al[i], Bh);
                    mma16816(acc[i][2 * jp],     Ah[i], Bl);
                    mma16816(acc[i][2 * jp + 1], Ah[i], Bh + 2);
                    mma16816(acc[i][2 * jp + 1], Al[i], Bh + 2);
                    mma16816(acc[i][2 * jp + 1], Ah[i], Bl + 2);
                }
            }
        }
        if (more) {
            storeA(nxt);
            CP_WAIT0();
        }
        __syncthreads();
    }

    // ---- epilogue: bias + relu -> hi/lo bf16 planes ----
#pragma unroll
    for (int j = 0; j < J; ++j) {
        const int col = n0 + wn * WN + j * 8 + tg * 2;
        if (col >= COUT) continue;
        const float2 bv = *reinterpret_cast<const float2*>(bias + col);
#pragma unroll
        for (int i = 0; i < 2; ++i) {
            const int r1 = row0 + wm * 32 + i * 16 + g;
            if (r1 < N) {
                float ox = fmaxf(acc[i][j][0] + bv.x, 0.f);
                float oy = fmaxf(acc[i][j][1] + bv.y, 0.f);
                float hx = __bfloat162float(__float2bfloat16(ox));
                float hy = __bfloat162float(__float2bfloat16(oy));
                *reinterpret_cast<uint32_t*>(outHi + (size_t)r1 * ostride + col) = pkbf(ox, oy);
                *reinterpret_cast<uint32_t*>(outLo + (size_t)r1 * ostride + col) = pkbf(ox - hx, oy - hy);
            }
            const int r2 = r1 + 8;
            if (r2 < N) {
                float ox = fmaxf(acc[i][j][2] + bv.x, 0.f);
                float oy = fmaxf(acc[i][j][3] + bv.y, 0.f);
                float hx = __bfloat162float(__float2bfloat16(ox));
                float hy = __bfloat162float(__float2bfloat16(oy));
                *reinterpret_cast<uint32_t*>(outHi + (size_t)r2 * ostride + col) = pkbf(ox, oy);
                *reinterpret_cast<uint32_t*>(outLo + (size_t)r2 * ostride + col) = pkbf(ox - hx, oy - hy);
            }
        }
    }
}

// ---------------------------------------------------------------------------
// Persistent per-tap rulebook HMMA GEMM over pre-split bf16 planes.
// A-loads: cp.async with zfill for invalid rows. Epilogue: red.v4 atomics.
// ---------------------------------------------------------------------------
template <int CIN, int NT, int NYT>
__global__ void __launch_bounds__(256, 2)
tap_mma_p(const __nv_bfloat16* __restrict__ Ahi, const __nv_bfloat16* __restrict__ Alo,
          const __nv_bfloat16* __restrict__ Whi, const __nv_bfloat16* __restrict__ Wlo,
          int COUTPAD, float* __restrict__ out, int ostride, int ocol, int COUT)
{
    constexpr int CH = CIN / 32;
    constexpr int WN = NT / 2;
    constexpr int J  = NT / 16;
    constexpr int JP = J / 2;
    constexpr int BQ = (NT * 8) / 256;
    constexpr uint32_t AB = 10240;
    constexpr uint32_t BB = NT * 80;
    constexpr int RSF = NT + 4;
    constexpr int NQ = NT / 4;

    __shared__ int sIn[128], sOut[128];
    extern __shared__ char dyn[];
    const uint32_t sb = (uint32_t)__cvta_generic_to_shared(dyn);
    float* sAcc = reinterpret_cast<float*>(dyn);

    const int t = threadIdx.x, lane = t & 31, w = t >> 5;
    const int wm = w >> 1, wn = w & 1;
    const int g = lane >> 2, tg = lane & 3;
    const int lrow = t >> 1;             // A cp.async row (0..127)
    const int asg = (t & 1) * 2;         // A seg base (0 or 2)
    const int local = lane & 7, grp = lane >> 3;
    const int arow = (grp & 1) * 8 + local;
    const int abyt = (grp >> 1) * 16;
    const int nloc = (grp >> 1) * 8 + local;
    const int bbyt = (grp & 1) * 16;

    const int nwork = g_nitems * NYT;

    for (int wk = blockIdx.x; wk < nwork; wk += gridDim.x) {
        const int item = (NYT == 1) ? wk : (wk >> 1);
        const int y    = (NYT == 1) ? 0  : (wk & 1);
        const int packed = g_items[item];
        const int tap = packed & 31;
        const int m0 = (packed >> 5) << 7;
        const int cn = g_cnt3[tap];
        const int n0 = y * NT;

        __syncthreads();   // prior epilogue's smem reads done
        if (t < 128) {
            const int m = m0 + t;
            if (m < cn) {
                int2 p = g_list3[(size_t)tap * NVOX + m];
                sIn[t] = p.x;
                sOut[t] = p.y;
            } else {
                sIn[t] = -1;
                sOut[t] = -1;
            }
        }
        __syncthreads();

        float acc[2][J][4];
#pragma unroll
        for (int i = 0; i < 2; ++i)
#pragma unroll
            for (int j = 0; j < J; ++j)
#pragma unroll
                for (int q = 0; q < 4; ++q) acc[i][j][q] = 0.f;

        const int gin = sIn[lrow];
        const uint32_t asz = (gin >= 0) ? 16u : 0u;
        const size_t abase = (size_t)(gin >= 0 ? gin : 0) * CIN;
        const __nv_bfloat16* aRowH = Ahi + abase;
        const __nv_bfloat16* aRowL = Alo + abase;

        auto issueA = [&](int it, int stage) {
            const int c0 = it * 32;
            const uint32_t off = (uint32_t)lrow * 80 + (uint32_t)asg * 16;
            const int eoff = c0 + asg * 8;
            cpasync16z(sb + (stage * 2 + 0) * AB + off,      aRowH + eoff,     asz);
            cpasync16z(sb + (stage * 2 + 0) * AB + off + 16, aRowH + eoff + 8, asz);
            cpasync16z(sb + (stage * 2 + 1) * AB + off,      aRowL + eoff,     asz);
            cpasync16z(sb + (stage * 2 + 1) * AB + off + 16, aRowL + eoff + 8, asz);
        };
        auto issueB = [&](int it, int stage) {
            const size_t base = ((size_t)tap * COUTPAD + n0) * CIN + it * 32;
#pragma unroll
            for (int q = 0; q < BQ; ++q) {
                const int e = t + q * 256;
                const int plane = e / (NT * 4);
                const int re = e - plane * (NT * 4);
                const int row = re >> 2, seg = re & 3;
                const __nv_bfloat16* src =
                    (plane ? Wlo : Whi) + base + (size_t)row * CIN + seg * 8;
                const uint32_t dst =
                    sb + 4 * AB + (uint32_t)(stage * 2 + plane) * BB + row * 80 + seg * 16;
                cpasync16(dst, src);
            }
        };

        issueA(0, 0);
        issueB(0, 0);
        CP_COMMIT();
        CP_WAIT0();
        __syncthreads();

#pragma unroll 1
        for (int it = 0; it < CH; ++it) {
            const int cur = it & 1, nxt = cur ^ 1;
            const bool more = (it + 1 < CH);
            if (more) {
                issueA(it + 1, nxt);
                issueB(it + 1, nxt);
                CP_COMMIT();
            }
            const uint32_t aH = sb + (uint32_t)(cur * 2 + 0) * AB;
            const uint32_t aL = sb + (uint32_t)(cur * 2 + 1) * AB;
            const uint32_t bH = sb + 4 * AB + (uint32_t)(cur * 2 + 0) * BB;
            const uint32_t bL = sb + 4 * AB + (uint32_t)(cur * 2 + 1) * BB;
#pragma unroll
            for (int ks = 0; ks < 2; ++ks) {
                uint32_t Ah[2][4], Al[2][4];
#pragma unroll
                for (int i = 0; i < 2; ++i) {
                    const uint32_t ao =
                        (uint32_t)((wm * 32 + i * 16 + arow) * 80 + ks * 32 + abyt);
                    ldsm4(Ah[i], aH + ao);
                    ldsm4(Al[i], aL + ao);
                }
#pragma unroll
                for (int jp = 0; jp < JP; ++jp) {
                    const uint32_t bo =
                        (uint32_t)((wn * WN + jp * 16 + nloc) * 80 + ks * 32 + bbyt);
                    uint32_t Bh[4], Bl[4];
                    ldsm4(Bh, bH + bo);
                    ldsm4(Bl, bL + bo);
#pragma unroll
                    for (int i = 0; i < 2; ++i) {
                        mma16816(acc[i][2 * jp],     Ah[i], Bh);
                        mma16816(acc[i][2 * jp],     Al[i], Bh);
                        mma16816(acc[i][2 * jp],     Ah[i], Bl);
                        mma16816(acc[i][2 * jp + 1], Ah[i], Bh + 2);
                        mma16816(acc[i][2 * jp + 1], Al[i], Bh + 2);
                        mma16816(acc[i][2 * jp + 1], Ah[i], Bl + 2);
                    }
                }
            }
            if (more) CP_WAIT0();
            __syncthreads();
        }

        // ---- epilogue: stage acc tile in smem, coalesced v4 reductions ----
#pragma unroll
        for (int j = 0; j < J; ++j) {
            const int col = wn * WN + j * 8 + tg * 2;
#pragma unroll
            for (int i = 0; i < 2; ++i) {
                const int r1 = wm * 32 + i * 16 + g;
                *reinterpret_cast<float2*>(&sAcc[r1 * RSF + col]) =
                    make_float2(acc[i][j][0], acc[i][j][1]);
                *reinterpret_cast<float2*>(&sAcc[(r1 + 8) * RSF + col]) =
                    make_float2(acc[i][j][2], acc[i][j][3]);
            }
        }
        __syncthreads();

        for (int e = t; e < 128 * NQ; e += 256) {
            const int row = e / NQ, q = e - row * NQ;
            const int ro = sOut[row];
            const int col0 = n0 + q * 4;
            if (ro >= 0 && col0 < COUT) {
                float4 v = *reinterpret_cast<const float4*>(&sAcc[row * RSF + q * 4]);
                red4(out + (size_t)ro * ostride + ocol + col0, v);
            }
        }
    }
}

// ---------------------------------------------------------------------------
// Flow conv (K=343, Cin=2, Cout=128): 512 threads, per-warp 4-row tap skip.
// Epilogue writes bf16 hi/lo planes.
// ---------------------------------------------------------------------------
__global__ void __launch_bounds__(512)
flow_conv(const float* __restrict__ flow, const int* __restrict__ nbr7,
          const float* __restrict__ W, const float* __restrict__ bias,
          __nv_bfloat16* __restrict__ outHi, __nv_bfloat16* __restrict__ outLo, int N)
{
    constexpr int KK = 343, BM = 64;
    __shared__ float sF[2][BM * 2];
    __shared__ float sW[2][256];
    __shared__ unsigned char sV[2][BM];

    const int t = threadIdx.x;
    const int warp = t >> 5, lane = t & 31;
    const int row0 = blockIdx.x * BM;

    float acc[4][4];
#pragma unroll
    for (int i = 0; i < 4; ++i)
#pragma unroll
        for (int j = 0; j < 4; ++j) acc[i][j] = 0.f;

    auto load_stage = [&](int k, int buf) {
        if (t < BM) {
            int r = row0 + t;
            int idx = (r < N) ? nbr7[(size_t)k * N + r] : -1;
            float2 v = make_float2(0.f, 0.f);
            if (idx >= 0) v = *reinterpret_cast<const float2*>(&flow[(size_t)idx * 2]);
            sF[buf][t * 2] = v.x;
            sF[buf][t * 2 + 1] = v.y;
            sV[buf][t] = (idx >= 0);
        }
        if (t < 256) sW[buf][t] = W[(size_t)k * 256 + t];
    };

    load_stage(0, 0);
    for (int k = 0; k < KK; ++k) {
        __syncthreads();
        if (k + 1 < KK) load_stage(k + 1, (k + 1) & 1);
        const int buf = k & 1;
        const bool myv = (lane < 4) && (sV[buf][warp * 4 + lane] != 0);
        if (__ballot_sync(0xffffffffu, myv)) {
            const float4 w0 = *reinterpret_cast<const float4*>(&sW[buf][lane * 4]);
            const float4 w1 = *reinterpret_cast<const float4*>(&sW[buf][128 + lane * 4]);
#pragma unroll
            for (int i = 0; i < 4; ++i) {
                const float f0 = sF[buf][(warp * 4 + i) * 2];
                const float f1 = sF[buf][(warp * 4 + i) * 2 + 1];
                acc[i][0] = fmaf(f0, w0.x, fmaf(f1, w1.x, acc[i][0]));
                acc[i][1] = fmaf(f0, w0.y, fmaf(f1, w1.y, acc[i][1]));
                acc[i][2] = fmaf(f0, w0.z, fmaf(f1, w1.z, acc[i][2]));
                acc[i][3] = fmaf(f0, w0.w, fmaf(f1, w1.w, acc[i][3]));
            }
        }
    }

    const float4 bv = *reinterpret_cast<const float4*>(&bias[lane * 4]);
#pragma unroll
    for (int i = 0; i < 4; ++i) {
        const int r = row0 + warp * 4 + i;
        if (r >= N) continue;
        float ox = fmaxf(acc[i][0] + bv.x, 0.f);
        float oy = fmaxf(acc[i][1] + bv.y, 0.f);
        float oz = fmaxf(acc[i][2] + bv.z, 0.f);
        float ow = fmaxf(acc[i][3] + bv.w, 0.f);
        float hx = __bfloat162float(__float2bfloat16(ox));
        float hy = __bfloat162float(__float2bfloat16(oy));
        float hz = __bfloat162float(__float2bfloat16(oz));
        float hw = __bfloat162float(__float2bfloat16(ow));
        *reinterpret_cast<uint2*>(outHi + (size_t)r * 128 + lane * 4) =
            make_uint2(pkbf(ox, oy), pkbf(oz, ow));
        *reinterpret_cast<uint2*>(outLo + (size_t)r * 128 + lane * 4) =
            make_uint2(pkbf(ox - hx, oy - hy), pkbf(oz - hz, ow - hw));
    }
}

__global__ void tail_copy(const float* __restrict__ ext,
                          const float* __restrict__ flow,
                          float* __restrict__ out, int N)
{
    int i = blockIdx.x * blockDim.x + threadIdx.x;
    if (i >= N * 8) return;
    int r = i >> 3, c = i & 7;
    float v = (c < 2) ? flow[(size_t)r * 2 + c] : ext[(size_t)r * 6 + (c - 2)];
    out[(size_t)r * 128 + 120 + c] = v;
}

// ---------------------------------------------------------------------------
extern "C" void kernel_launch(void* const* d_in, const int* in_sizes, int n_in,
                              void* d_out, int out_size)
{
    const float* extr  = (const float*)d_in[0];
    const float* flow  = (const float*)d_in[1];
    const float* corrf = (const float*)d_in[2];
    const int*   nbr3  = (const int*)  d_in[3];
    const int*   nbr7  = (const int*)  d_in[4];
    const float* Wc1   = (const float*)d_in[5];
    const float* bc1   = (const float*)d_in[6];
    const float* Wc2   = (const float*)d_in[7];
    const float* bc2   = (const float*)d_in[8];
    const float* Wf1   = (const float*)d_in[9];
    const float* bf1   = (const float*)d_in[10];
    const float* Wf2   = (const float*)d_in[11];
    const float* bf2   = (const float*)d_in[12];
    const float* Wcat  = (const float*)d_in[13];
    const float* bcat  = (const float*)d_in[14];
    float* out = (float*)d_out;

    const int N = in_sizes[0] / 6;

    float* p_cat;
    __nv_bfloat16 *p_c1h, *p_c1l, *p_f1h, *p_f1l, *p_cath, *p_catl;
    cudaGetSymbolAddress((void**)&p_cat,  g_cat);
    cudaGetSymbolAddress((void**)&p_c1h,  g_c1h);
    cudaGetSymbolAddress((void**)&p_c1l,  g_c1l);
    cudaGetSymbolAddress((void**)&p_f1h,  g_f1h);
    cudaGetSymbolAddress((void**)&p_f1l,  g_f1l);
    cudaGetSymbolAddress((void**)&p_cath, g_cath);
    cudaGetSymbolAddress((void**)&p_catl, g_catl);
    __nv_bfloat16 *c1h, *c1l, *c2h, *c2l, *f2h, *f2l, *cth, *ctl;
    cudaGetSymbolAddress((void**)&c1h, gW_c1_hi);
    cudaGetSymbolAddress((void**)&c1l, gW_c1_lo);
    cudaGetSymbolAddress((void**)&c2h, gW_c2_hi);
    cudaGetSymbolAddress((void**)&c2l, gW_c2_lo);
    cudaGetSymbolAddress((void**)&f2h, gW_f2_hi);
    cudaGetSymbolAddress((void**)&f2l, gW_f2_lo);
    cudaGetSymbolAddress((void**)&cth, gW_ct_hi);
    cudaGetSymbolAddress((void**)&ctl, gW_ct_lo);

    int nsm = 148;
    cudaDeviceGetAttribute(&nsm, cudaDevAttrMultiProcessorCount, 0);
    const int pgrid = nsm * 2;

    static cudaStream_t s1 = nullptr, s2 = nullptr;
    static cudaEvent_t evFork = nullptr, evRB = nullptr, evF2 = nullptr;
    if (!s1) {
        cudaStreamCreateWithFlags(&s1, cudaStreamNonBlocking);
        cudaStreamCreateWithFlags(&s2, cudaStreamNonBlocking);
        cudaEventCreateWithFlags(&evFork, cudaEventDisableTiming);
        cudaEventCreateWithFlags(&evRB,   cudaEventDisableTiming);
        cudaEventCreateWithFlags(&evF2,   cudaEventDisableTiming);
    }

    const int mblk = (N + 127) / 128;
    auto dsm = [](int NT) { return 4 * 10240 + 4 * NT * 80; };

    cudaFuncSetAttribute(tmma<1, 324, 352, 128>,
                         cudaFuncAttributeMaxDynamicSharedMemorySize, dsm(128));
    cudaFuncSetAttribute(tap_mma_p<256, 96, 2>,
                         cudaFuncAttributeMaxDynamicSharedMemorySize, dsm(96));
    cudaFuncSetAttribute(tap_mma_p<128, 64, 1>,
                         cudaFuncAttributeMaxDynamicSharedMemorySize, dsm(64));
    cudaFuncSetAttribute(tap_mma_p<256, 128, 1>,
                         cudaFuncAttributeMaxDynamicSharedMemorySize, dsm(128));

    // ---- fork side streams off the (captured) legacy stream ----
    cudaEventRecord(evFork, 0);
    cudaStreamWaitEvent(s1, evFork, 0);
    cudaStreamWaitEvent(s2, evFork, 0);

    // ---- main stream: c1 chain (writes bf16 hi/lo planes) ----
    prep_w<1, 324, 256, 352, 256><<<(1 * 256 * 352 + 255) / 256, 256>>>(Wc1, c1h, c1l);
    tmma<1, 324, 352, 128><<<dim3(mblk, 2), 256, dsm(128)>>>(
        corrf, 324, c1h, c1l, 256, bc1, p_c1h, p_c1l, 256, 256, N);

    // ---- s1: rulebook + c2 weights + cat bias init ----
    zero_cnt<<<1, 32, 0, s1>>>();
    build_list<<<dim3((N + 255) / 256, 27), 256, 0, s1>>>(nbr3, N);
    sched<<<1, 32, 0, s1>>>();
    prep_w<27, 256, 192, 256, 192><<<(27 * 192 * 256 + 255) / 256, 256, 0, s1>>>(Wc2, c2h, c2l);
    init_cat<<<((long)N * 256 + 255) / 256, 256, 0, s1>>>(p_cat, bc2, bf2, N);
    cudaEventRecord(evRB, s1);

    // ---- s2: flow chain + misc prep + f2 ----
    flow_conv<<<(N + 63) / 64, 512, 0, s2>>>(flow, nbr7, Wf1, bf1, p_f1h, p_f1l, N);
    prep_w<27, 128, 64, 128, 64><<<(27 * 64 * 128 + 255) / 256, 256, 0, s2>>>(Wf2, f2h, f2l);
    prep_w<27, 256, 120, 256, 128><<<(27 * 128 * 256 + 255) / 256, 256, 0, s2>>>(Wcat, cth, ctl);
    init_bias<<<((long)N * 120 + 255) / 256, 256, 0, s2>>>(out, 128, 0, bcat, 120, N);
    tail_copy<<<(N * 8 + 255) / 256, 256, 0, s2>>>(extr, flow, out, N);
    cudaStreamWaitEvent(s2, evRB, 0);      // needs rulebook + init_cat
    tap_mma_p<128, 64, 1><<<pgrid, 256, dsm(64), s2>>>(
        p_f1h, p_f1l, f2h, f2l, 64, p_cat, 256, 192, 64);
    cudaEventRecord(evF2, s2);

    // ---- main: c2 (needs rulebook + init_cat + c1) ----
    cudaStreamWaitEvent(0, evRB, 0);
    tap_mma_p<256, 96, 2><<<pgrid, 256, dsm(96)>>>(
        p_c1h, p_c1l, c2h, c2l, 192, p_cat, 256, 0, 192);

    // ---- main: relu+split cat -> planes (needs c2 [stream order] + f2 [evF2]) ----
    cudaStreamWaitEvent(0, evF2, 0);
    relu_split<<<((long)N * 256 / 4 + 255) / 256, 256>>>(p_cat, p_cath, p_catl, (long)N * 256);

    // ---- main: final conv + relu ----
    tap_mma_p<256, 128, 1><<<pgrid, 256, dsm(128)>>>(
        p_cath, p_catl, cth, ctl, 128, out, 128, 0, 120);
    relu_region<<<((long)N * 120 + 255) / 256, 256>>>(out, 128, 0, 120, N);
}